// round 12
// baseline (speedup 1.0000x reference)
#include <cuda_runtime.h>

#define N_NODES 200000
#define C_DIM 256
#define H_DIM 64
#define K_DIM 3
#define G_DIM 512

// ---------------- scratch (device globals; no allocation allowed) ----------
__device__ float    g_scores[N_NODES * K_DIM];
__device__ unsigned g_menc[G_DIM * K_DIM];
__device__ float    g_denom[G_DIM * K_DIM];
__device__ int      g_argmin[G_DIM * K_DIM];

// ---------------- helpers --------------------------------------------------
__device__ __forceinline__ unsigned fenc(float f) {
    unsigned u = __float_as_uint(f);
    return u ^ ((u >> 31) ? 0xFFFFFFFFu : 0x80000000u);
}
__device__ __forceinline__ float fdec(unsigned e) {
    unsigned u = (e & 0x80000000u) ? (e ^ 0x80000000u) : ~e;
    return __uint_as_float(u);
}
__device__ __forceinline__ float lrelu(float v) { return v > 0.f ? v : 0.01f * v; }
__device__ __forceinline__ int clampg(int g) { return min(max(g, 0), G_DIM - 1); }

__device__ __forceinline__ void fma2(unsigned long long& acc,
                                     unsigned long long a, unsigned long long b) {
    asm("fma.rn.f32x2 %0, %1, %2, %0;" : "+l"(acc) : "l"(a), "l"(b));
}
__device__ __forceinline__ unsigned long long dup2(float v) {
    unsigned long long r;
    unsigned u = __float_as_uint(v);
    asm("mov.b64 %0, {%1, %1};" : "=l"(r) : "r"(u));
    return r;
}
__device__ __forceinline__ void unpk2(unsigned long long v, float& lo, float& hi) {
    unsigned a, b;
    asm("mov.b64 {%0, %1}, %2;" : "=r"(a), "=r"(b) : "l"(v));
    lo = __uint_as_float(a); hi = __uint_as_float(b);
}

// ---------------- K0: init reduction buffers -------------------------------
__global__ void k_init() {
    int i = blockIdx.x * blockDim.x + threadIdx.x;
    if (i < G_DIM * K_DIM) {
        g_menc[i]   = 0u;
        g_denom[i]  = 0.f;
        g_argmin[i] = N_NODES;
    }
}

// ---------------- K1: scores (8 rows x 4 h-pairs, reg-buffered pipeline) ---
#define SC_THREADS 128
#define SC_ROWS 128       // rows per block
#define SC_CHUNK 16       // k-depth per stage (16 chunks)
#define XD_PAD 132        // u64 stride for xs_d rows
#define WF_PAD 36         // u64 stride for W1f2 rows (32 hp + pad)

__global__ __launch_bounds__(SC_THREADS, 4) void k_scores(
    const float* __restrict__ x, const int* __restrict__ batch,
    const float* __restrict__ W1, const float* __restrict__ b1,
    const float* __restrict__ W2, const float* __restrict__ b2)
{
    // xs_d[k][row] = {x,x} packed            (16*132*8 = 16.9 KB)
    // W1f2[k][hp]  = natural float2 of W1    (16*36*8  =  4.6 KB)
    __shared__ __align__(16) unsigned long long xs_d[SC_CHUNK][XD_PAD];
    __shared__ __align__(16) unsigned long long W1f2[SC_CHUNK][WF_PAD];
    __shared__ float W2s[H_DIM * K_DIM];
    __shared__ float b1s[H_DIM];
    __shared__ float b2s[K_DIM];

    const int t  = threadIdx.x;
    const int r0 = blockIdx.x * SC_ROWS;
    const int lh = t & 7;           // h-lane: h in [lh*8, lh*8+8)
    const int rb = (t >> 3) * 8;    // 8-row group

    for (int i = t; i < H_DIM * K_DIM; i += SC_THREADS) W2s[i] = W2[i];
    if (t < H_DIM) b1s[t] = b1[t];
    if (t < K_DIM) b2s[t] = b2[t];

    unsigned long long acc[8][4];   // 8 rows x 4 h-pairs
#pragma unroll
    for (int r = 0; r < 8; r++)
#pragma unroll
        for (int p = 0; p < 4; p++) acc[r][p] = 0ull;

    // staging registers (loaded for chunk c+1 while computing chunk c)
    float4 xv[4];   // 4 float4 of x: rows (t>>2)-pattern
    float4 wv[2];   // 2 float4 of W1 chunk
    const int xrow = t >> 2;            // 4 threads per row
    const int xc4  = t & 3;             // float4 index within 16-k slice
    const int wk   = t >> 4;            // W: k row (0..7 for 128 thr? -> f loop)
    // x: 128 rows * 4 float4 = 512 float4; thread handles f = t + 128*i (i=0..3)
    //    f -> row = f >> 2, c4 = f & 3
    // W: 16 k * 16 float4 = 256 float4; thread handles f = t, t+128
    //    f -> k = f >> 4, q = f & 15

    auto load_stage = [&](int c0) {
#pragma unroll
        for (int i = 0; i < 4; i++) {
            int f = t + SC_THREADS * i;
            int row = f >> 2, c4 = f & 3;
            if (r0 + row < N_NODES)
                xv[i] = *(const float4*)(x + (size_t)(r0 + row) * C_DIM + c0 + 4 * c4);
            else
                xv[i] = make_float4(0.f, 0.f, 0.f, 0.f);
        }
#pragma unroll
        for (int i = 0; i < 2; i++) {
            int f = t + SC_THREADS * i;
            int k = f >> 4, q = f & 15;
            wv[i] = *(const float4*)(W1 + (size_t)(c0 + k) * H_DIM + 4 * q);
        }
    };
    auto store_stage = [&]() {
#pragma unroll
        for (int i = 0; i < 4; i++) {
            int f = t + SC_THREADS * i;
            int row = f >> 2, c4 = f & 3;
            xs_d[4 * c4 + 0][row] = dup2(xv[i].x);
            xs_d[4 * c4 + 1][row] = dup2(xv[i].y);
            xs_d[4 * c4 + 2][row] = dup2(xv[i].z);
            xs_d[4 * c4 + 3][row] = dup2(xv[i].w);
        }
#pragma unroll
        for (int i = 0; i < 2; i++) {
            int f = t + SC_THREADS * i;
            int k = f >> 4, q = f & 15;
            // natural float2 pairs: two u64 per float4
            float2 lo = make_float2(wv[i].x, wv[i].y);
            float2 hi = make_float2(wv[i].z, wv[i].w);
            *(float2*)&W1f2[k][2 * q + 0] = lo;
            *(float2*)&W1f2[k][2 * q + 1] = hi;
        }
    };

    load_stage(0);
    for (int c = 0; c < C_DIM / SC_CHUNK; c++) {
        __syncthreads();          // smem free (prev compute done)
        store_stage();
        __syncthreads();          // smem ready
        if (c + 1 < C_DIM / SC_CHUNK) load_stage((c + 1) * SC_CHUNK);
#pragma unroll
        for (int j = 0; j < SC_CHUNK; j++) {
            ulonglong2 xa = *(const ulonglong2*)&xs_d[j][rb + 0];
            ulonglong2 xb = *(const ulonglong2*)&xs_d[j][rb + 2];
            ulonglong2 xc = *(const ulonglong2*)&xs_d[j][rb + 4];
            ulonglong2 xd = *(const ulonglong2*)&xs_d[j][rb + 6];
            unsigned long long xr[8] = {xa.x, xa.y, xb.x, xb.y,
                                        xc.x, xc.y, xd.x, xd.y};
            ulonglong2 wa = *(const ulonglong2*)&W1f2[j][lh * 4 + 0];
            ulonglong2 wb = *(const ulonglong2*)&W1f2[j][lh * 4 + 2];
            unsigned long long wf[4] = {wa.x, wa.y, wb.x, wb.y};
#pragma unroll
            for (int r = 0; r < 8; r++)
#pragma unroll
                for (int p = 0; p < 4; p++)
                    fma2(acc[r][p], xr[r], wf[p]);
        }
    }

    // epilogue: bias + lrelu + @W2 partials (8 rows x 8 h), butterfly over lh
    float scp[8][K_DIM];
#pragma unroll
    for (int r = 0; r < 8; r++)
#pragma unroll
        for (int k = 0; k < K_DIM; k++) scp[r][k] = 0.f;

#pragma unroll
    for (int r = 0; r < 8; r++)
#pragma unroll
        for (int p = 0; p < 4; p++) {
            float lo, hi; unpk2(acc[r][p], lo, hi);
            int h0 = lh * 8 + 2 * p, h1 = h0 + 1;
            float hv0 = lrelu(lo + b1s[h0]);
            float hv1 = lrelu(hi + b1s[h1]);
#pragma unroll
            for (int k = 0; k < K_DIM; k++) {
                scp[r][k] = fmaf(hv0, W2s[h0 * K_DIM + k], scp[r][k]);
                scp[r][k] = fmaf(hv1, W2s[h1 * K_DIM + k], scp[r][k]);
            }
        }

    const unsigned FULL = 0xFFFFFFFFu;
#pragma unroll
    for (int o = 1; o < 8; o <<= 1)
#pragma unroll
        for (int r = 0; r < 8; r++)
#pragma unroll
            for (int k = 0; k < K_DIM; k++)
                scp[r][k] += __shfl_xor_sync(FULL, scp[r][k], o);

    // lane lh writes row rb + lh
    int n = r0 + rb + lh;
    if (n < N_NODES) {
        int g = clampg(batch[n]);
#pragma unroll
        for (int k = 0; k < K_DIM; k++) {
            float s = scp[lh][k] + b2s[k];
            g_scores[(size_t)n * K_DIM + k] = s;
            atomicMax(&g_menc[g * K_DIM + k], fenc(s));
        }
    }
}

// ---------------- K2: exp-sum (denom) + argmin of argmax -------------------
__global__ void k_reduce(const int* __restrict__ batch) {
    int n = blockIdx.x * blockDim.x + threadIdx.x;
    if (n >= N_NODES) return;
    int g = clampg(batch[n]);
#pragma unroll
    for (int k = 0; k < K_DIM; k++) {
        float s = g_scores[(size_t)n * K_DIM + k];
        float m = fdec(g_menc[g * K_DIM + k]);
        float e = expf(s - m);
        atomicAdd(&g_denom[g * K_DIM + k], e);
        if (s == m) atomicMin(&g_argmin[g * K_DIM + k], n);
    }
}

// ---------------- K3: gather + feat@Wh + lrelu (128 blocks, r-split 4) -----
#define GPB 4
#define KF_THREADS 1024
__global__ __launch_bounds__(KF_THREADS) void k_final(
    const float* __restrict__ x, const int* __restrict__ batch,
    const float* __restrict__ Wh, const float* __restrict__ bh,
    float* __restrict__ out)
{
    __shared__ float feat[GPB][K_DIM * C_DIM];
    __shared__ float sg_s[GPB][K_DIM];
    __shared__ int   idx_s[GPB][K_DIM];

    const int t  = threadIdx.x;
    const int g0 = blockIdx.x * GPB;

    if (t < GPB * K_DIM) {
        int gi = t / K_DIM, k = t % K_DIM;
        int g = g0 + gi;
        int idx = min(g_argmin[g * K_DIM + k], N_NODES - 1);
        int gb = clampg(batch[idx]);
        float m = fdec(g_menc[gb * K_DIM + k]);
        float sg = expf(g_scores[(size_t)idx * K_DIM + k] - m) / g_denom[gb * K_DIM + k];
        sg_s[gi][k] = sg;
        idx_s[gi][k] = idx;
    }
    __syncthreads();

    for (int idx = t; idx < GPB * K_DIM * C_DIM; idx += KF_THREADS) {
        int gi = idx / (K_DIM * C_DIM);
        int rem = idx - gi * (K_DIM * C_DIM);
        int k = rem >> 8, c = rem & 255;
        feat[gi][rem] = x[(size_t)idx_s[gi][k] * C_DIM + c] * sg_s[gi][k];
    }
    __syncthreads();

    const int col = t & 255;
    const int rs  = t >> 8;
    float acc[GPB];
#pragma unroll
    for (int gi = 0; gi < GPB; gi++) acc[gi] = 0.f;

    const int rbeg = rs * 192;
#pragma unroll 8
    for (int r = rbeg; r < rbeg + 192; r++) {
        float wv = __ldg(&Wh[(size_t)r * C_DIM + col]);
#pragma unroll
        for (int gi = 0; gi < GPB; gi++) acc[gi] = fmaf(feat[gi][r], wv, acc[gi]);
    }

    __syncthreads();
    float* red = &feat[0][0];
    if (rs > 0) {
#pragma unroll
        for (int gi = 0; gi < GPB; gi++)
            red[((rs - 1) * GPB + gi) * C_DIM + col] = acc[gi];
    }
    __syncthreads();
    if (rs == 0) {
        float bhv = __ldg(&bh[col]);
#pragma unroll
        for (int gi = 0; gi < GPB; gi++) {
            float v = acc[gi]
                    + red[(0 * GPB + gi) * C_DIM + col]
                    + red[(1 * GPB + gi) * C_DIM + col]
                    + red[(2 * GPB + gi) * C_DIM + col]
                    + bhv;
            out[(size_t)(g0 + gi) * C_DIM + col] = lrelu(v);
        }
    }
}

// ---------------- launch: bind inputs by UNIQUE element count ---------------
extern "C" void kernel_launch(void* const* d_in, const int* in_sizes, int n_in,
                              void* d_out, int out_size) {
    const int want[8] = {51200000, 200000, 16384, 64, 192, 3, 196608, 256};
    const void* p[8];
    for (int r = 0; r < 8; r++) p[r] = (r < n_in) ? d_in[r] : nullptr;
    for (int r = 0; r < 8; r++)
        for (int i = 0; i < n_in; i++)
            if (in_sizes[i] == want[r]) { p[r] = d_in[i]; break; }

    const float* x     = (const float*)p[0];
    const int*   batch = (const int*)p[1];
    const float* W1    = (const float*)p[2];
    const float* b1    = (const float*)p[3];
    const float* W2    = (const float*)p[4];
    const float* b2    = (const float*)p[5];
    const float* Wh    = (const float*)p[6];
    const float* bh    = (const float*)p[7];
    float* out = (float*)d_out;

    k_init<<<(G_DIM * K_DIM + 255) / 256, 256>>>();
    k_scores<<<(N_NODES + SC_ROWS - 1) / SC_ROWS, SC_THREADS>>>(x, batch, W1, b1, W2, b2);
    k_reduce<<<(N_NODES + 255) / 256, 256>>>(batch);
    k_final<<<G_DIM / GPB, KF_THREADS>>>(x, batch, Wh, bh, out);
}

// round 14
// speedup vs baseline: 1.1870x; 1.1870x over previous
#include <cuda_runtime.h>
#include <cuda_bf16.h>
#include <cstdint>

#define N_NODES 200000
#define C_DIM 256
#define H_DIM 64
#define K_DIM 3
#define G_DIM 512

// ---------------- scratch (device globals; no allocation allowed) ----------
__device__ float    g_scores[N_NODES * K_DIM];
__device__ unsigned g_menc[G_DIM * K_DIM];
__device__ float    g_denom[G_DIM * K_DIM];
__device__ int      g_argmin[G_DIM * K_DIM];

// ---------------- helpers --------------------------------------------------
__device__ __forceinline__ unsigned fenc(float f) {
    unsigned u = __float_as_uint(f);
    return u ^ ((u >> 31) ? 0xFFFFFFFFu : 0x80000000u);
}
__device__ __forceinline__ float fdec(unsigned e) {
    unsigned u = (e & 0x80000000u) ? (e ^ 0x80000000u) : ~e;
    return __uint_as_float(u);
}
__device__ __forceinline__ float lrelu(float v) { return v > 0.f ? v : 0.01f * v; }
__device__ __forceinline__ int clampg(int g) { return min(max(g, 0), G_DIM - 1); }

// 3-level bf16 split: v = L0 + L1 + L2 (+ O(2^-26 |v|))
__device__ __forceinline__ void split3(float v, uint16_t& e0, uint16_t& e1, uint16_t& e2) {
    __nv_bfloat16 a = __float2bfloat16(v);
    float r = v - __bfloat162float(a);
    __nv_bfloat16 b = __float2bfloat16(r);
    float r2 = r - __bfloat162float(b);
    __nv_bfloat16 c = __float2bfloat16(r2);
    e0 = __bfloat16_as_ushort(a);
    e1 = __bfloat16_as_ushort(b);
    e2 = __bfloat16_as_ushort(c);
}
__device__ __forceinline__ uint32_t pack2(uint16_t lo, uint16_t hi) {
    return (uint32_t)lo | ((uint32_t)hi << 16);
}
// mma.sync m16n8k16 bf16 -> f32 (sm_80+ PTX; legal on plain compute_103)
__device__ __forceinline__ void mma_bf16(float* d, const uint32_t* a, uint2 b) {
    asm volatile(
        "mma.sync.aligned.m16n8k16.row.col.f32.bf16.bf16.f32 "
        "{%0,%1,%2,%3}, {%4,%5,%6,%7}, {%8,%9}, {%0,%1,%2,%3};"
        : "+f"(d[0]), "+f"(d[1]), "+f"(d[2]), "+f"(d[3])
        : "r"(a[0]), "r"(a[1]), "r"(a[2]), "r"(a[3]), "r"(b.x), "r"(b.y));
}

// ---------------- K0: init reduction buffers -------------------------------
__global__ void k_init() {
    int i = blockIdx.x * blockDim.x + threadIdx.x;
    if (i < G_DIM * K_DIM) {
        g_menc[i]   = 0u;
        g_denom[i]  = 0.f;
        g_argmin[i] = N_NODES;
    }
}

// ---------------- K1: scores via mma.sync bf16 3-level split ---------------
// CTA: 128 thr (4 warps), 128 rows. Warp: 32 rows x 64 h. K chunks of 32.
#define SC_M 128
#define KC 32             // fp32-k per chunk
#define A_STRIDE 10       // uint2 per row (8 used + pad) -> optimal 2-wavefront LDS.64
#define B_STRIDE 10

__global__ __launch_bounds__(128, 4) void k_scores_mma(
    const float* __restrict__ x, const int* __restrict__ batch,
    const float* __restrict__ W1, const float* __restrict__ b1,
    const float* __restrict__ W2, const float* __restrict__ b2)
{
    __shared__ uint2 AU[3][SC_M * A_STRIDE];   // 30720 B
    __shared__ uint2 BU[3][H_DIM * B_STRIDE];  // 15360 B
    __shared__ float W2s[H_DIM * K_DIM];
    __shared__ float b1s[H_DIM];
    __shared__ float b2s[K_DIM];

    const int t    = threadIdx.x;
    const int wid  = t >> 5, lane = t & 31;
    const int g    = lane >> 2, tig = lane & 3;
    const int r0   = blockIdx.x * SC_M;
    const int rw   = wid * 32;                 // warp's row slice base (in CTA)

    for (int i = t; i < H_DIM * K_DIM; i += 128) W2s[i] = W2[i];
    if (t < H_DIM) b1s[t] = b1[t];
    if (t < K_DIM) b2s[t] = b2[t];

    float acc[2][8][4];
#pragma unroll
    for (int m = 0; m < 2; m++)
#pragma unroll
        for (int n = 0; n < 8; n++)
#pragma unroll
            for (int e = 0; e < 4; e++) acc[m][n][e] = 0.f;

    // term order: A-levels grouped for frag reuse
    const int Aseq[6] = {0, 0, 0, 1, 1, 2};
    const int Bseq[6] = {0, 1, 2, 0, 1, 0};

    for (int c0 = 0; c0 < C_DIM; c0 += KC) {
        __syncthreads();   // prior chunk's compute done
        // ---- stage x tile: 128 rows x 32 k, 3 levels -----------------------
        uint32_t* AW[3] = {(uint32_t*)AU[0], (uint32_t*)AU[1], (uint32_t*)AU[2]};
#pragma unroll
        for (int i = 0; i < 8; i++) {
            int f = t + 128 * i;               // 1024 float4
            int row = f >> 3, c = f & 7;       // c: float4 index (k=4c..4c+3)
            float4 v = (r0 + row < N_NODES)
                ? *(const float4*)(x + (size_t)(r0 + row) * C_DIM + c0 + 4 * c)
                : make_float4(0.f, 0.f, 0.f, 0.f);
            uint16_t ex[4][3];
            split3(v.x, ex[0][0], ex[0][1], ex[0][2]);
            split3(v.y, ex[1][0], ex[1][1], ex[1][2]);
            split3(v.z, ex[2][0], ex[2][1], ex[2][2]);
            split3(v.w, ex[3][0], ex[3][1], ex[3][2]);
#pragma unroll
            for (int pp = 0; pp < 2; pp++) {   // pairs (4c,4c+1) and (4c+2,4c+3)
                int p  = 2 * c + pp;
                int kt = p >> 3, rr = p & 7;
                int off = row * (2 * A_STRIDE) + (kt * 4 + (rr & 3)) * 2 + (rr >> 2);
#pragma unroll
                for (int L = 0; L < 3; L++)
                    AW[L][off] = pack2(ex[2 * pp][L], ex[2 * pp + 1][L]);
            }
        }
        // ---- stage W1^T tile: 16 k-pairs x 64 n, 3 levels ------------------
        uint32_t* BW[3] = {(uint32_t*)BU[0], (uint32_t*)BU[1], (uint32_t*)BU[2]};
#pragma unroll
        for (int i = 0; i < 8; i++) {
            int idx = t + 128 * i;             // 1024 (p,n) items
            int n = idx & 63, p = idx >> 6;
            float w0 = __ldg(&W1[(size_t)(c0 + 2 * p) * H_DIM + n]);
            float w1 = __ldg(&W1[(size_t)(c0 + 2 * p + 1) * H_DIM + n]);
            uint16_t e0[3], e1[3];
            split3(w0, e0[0], e0[1], e0[2]);
            split3(w1, e1[0], e1[1], e1[2]);
            int kt = p >> 3, rr = p & 7;
            int off = n * (2 * B_STRIDE) + (kt * 4 + (rr & 3)) * 2 + (rr >> 2);
#pragma unroll
            for (int L = 0; L < 3; L++)
                BW[L][off] = pack2(e0[L], e1[L]);
        }
        __syncthreads();
        // ---- compute: 2 k16-tiles x 6 terms x (2m x 8n) mma ----------------
#pragma unroll
        for (int kt = 0; kt < 2; kt++) {
            int lastA = -1;
            uint32_t a[2][4];
#pragma unroll
            for (int t6 = 0; t6 < 6; t6++) {
                int La = Aseq[t6], Lb = Bseq[t6];
                if (La != lastA) {
                    lastA = La;
#pragma unroll
                    for (int m = 0; m < 2; m++) {
                        uint2 lo = AU[La][(rw + m * 16 + g) * A_STRIDE + kt * 4 + tig];
                        uint2 hi = AU[La][(rw + m * 16 + g + 8) * A_STRIDE + kt * 4 + tig];
                        a[m][0] = lo.x; a[m][1] = hi.x; a[m][2] = lo.y; a[m][3] = hi.y;
                    }
                }
#pragma unroll
                for (int nt = 0; nt < 8; nt++) {
                    uint2 b = BU[Lb][(nt * 8 + g) * B_STRIDE + kt * 4 + tig];
                    mma_bf16(acc[0][nt], a[0], b);
                    mma_bf16(acc[1][nt], a[1], b);
                }
            }
        }
    }

    // ---- epilogue: +b1, lrelu, @W2, reduce over tig lanes, atomics ---------
    float sc[4][K_DIM];                        // row slots: mt*2 + (0:row g, 1:row g+8)
#pragma unroll
    for (int s = 0; s < 4; s++)
#pragma unroll
        for (int k = 0; k < K_DIM; k++) sc[s][k] = 0.f;

#pragma unroll
    for (int m = 0; m < 2; m++)
#pragma unroll
        for (int nt = 0; nt < 8; nt++) {
            int cA = nt * 8 + 2 * tig, cB = cA + 1;
            float h0 = lrelu(acc[m][nt][0] + b1s[cA]);
            float h1 = lrelu(acc[m][nt][1] + b1s[cB]);
            float h2 = lrelu(acc[m][nt][2] + b1s[cA]);
            float h3 = lrelu(acc[m][nt][3] + b1s[cB]);
#pragma unroll
            for (int k = 0; k < K_DIM; k++) {
                sc[m * 2 + 0][k] += h0 * W2s[cA * K_DIM + k] + h1 * W2s[cB * K_DIM + k];
                sc[m * 2 + 1][k] += h2 * W2s[cA * K_DIM + k] + h3 * W2s[cB * K_DIM + k];
            }
        }

    const unsigned FULL = 0xFFFFFFFFu;
#pragma unroll
    for (int o = 1; o < 4; o <<= 1)
#pragma unroll
        for (int s = 0; s < 4; s++)
#pragma unroll
            for (int k = 0; k < K_DIM; k++)
                sc[s][k] += __shfl_xor_sync(FULL, sc[s][k], o);

    if (tig == 0) {
#pragma unroll
        for (int s = 0; s < 4; s++) {
            int m = s >> 1, half = s & 1;
            int n = r0 + rw + m * 16 + half * 8 + g;
            if (n < N_NODES) {
                int gb = clampg(batch[n]);
#pragma unroll
                for (int k = 0; k < K_DIM; k++) {
                    float v = sc[s][k] + b2s[k];
                    g_scores[(size_t)n * K_DIM + k] = v;
                    atomicMax(&g_menc[gb * K_DIM + k], fenc(v));
                }
            }
        }
    }
}

// ---------------- K2: exp-sum (denom) + argmin of argmax -------------------
__global__ void k_reduce(const int* __restrict__ batch) {
    int n = blockIdx.x * blockDim.x + threadIdx.x;
    if (n >= N_NODES) return;
    int g = clampg(batch[n]);
#pragma unroll
    for (int k = 0; k < K_DIM; k++) {
        float s = g_scores[(size_t)n * K_DIM + k];
        float m = fdec(g_menc[g * K_DIM + k]);
        float e = expf(s - m);
        atomicAdd(&g_denom[g * K_DIM + k], e);
        if (s == m) atomicMin(&g_argmin[g * K_DIM + k], n);
    }
}

// ---------------- K3: gather + feat@Wh + lrelu (128 blocks, r-split 4) -----
#define GPB 4
#define KF_THREADS 1024
__global__ __launch_bounds__(KF_THREADS) void k_final(
    const float* __restrict__ x, const int* __restrict__ batch,
    const float* __restrict__ Wh, const float* __restrict__ bh,
    float* __restrict__ out)
{
    __shared__ float feat[GPB][K_DIM * C_DIM];
    __shared__ float sg_s[GPB][K_DIM];
    __shared__ int   idx_s[GPB][K_DIM];

    const int t  = threadIdx.x;
    const int g0 = blockIdx.x * GPB;

    if (t < GPB * K_DIM) {
        int gi = t / K_DIM, k = t % K_DIM;
        int g = g0 + gi;
        int idx = min(g_argmin[g * K_DIM + k], N_NODES - 1);
        int gb = clampg(batch[idx]);
        float m = fdec(g_menc[gb * K_DIM + k]);
        float sg = expf(g_scores[(size_t)idx * K_DIM + k] - m) / g_denom[gb * K_DIM + k];
        sg_s[gi][k] = sg;
        idx_s[gi][k] = idx;
    }
    __syncthreads();

    for (int idx = t; idx < GPB * K_DIM * C_DIM; idx += KF_THREADS) {
        int gi = idx / (K_DIM * C_DIM);
        int rem = idx - gi * (K_DIM * C_DIM);
        int k = rem >> 8, c = rem & 255;
        feat[gi][rem] = x[(size_t)idx_s[gi][k] * C_DIM + c] * sg_s[gi][k];
    }
    __syncthreads();

    const int col = t & 255;
    const int rs  = t >> 8;
    float acc[GPB];
#pragma unroll
    for (int gi = 0; gi < GPB; gi++) acc[gi] = 0.f;

    const int rbeg = rs * 192;
#pragma unroll 8
    for (int r = rbeg; r < rbeg + 192; r++) {
        float wv = __ldg(&Wh[(size_t)r * C_DIM + col]);
#pragma unroll
        for (int gi = 0; gi < GPB; gi++) acc[gi] = fmaf(feat[gi][r], wv, acc[gi]);
    }

    __syncthreads();
    float* red = &feat[0][0];
    if (rs > 0) {
#pragma unroll
        for (int gi = 0; gi < GPB; gi++)
            red[((rs - 1) * GPB + gi) * C_DIM + col] = acc[gi];
    }
    __syncthreads();
    if (rs == 0) {
        float bhv = __ldg(&bh[col]);
#pragma unroll
        for (int gi = 0; gi < GPB; gi++) {
            float v = acc[gi]
                    + red[(0 * GPB + gi) * C_DIM + col]
                    + red[(1 * GPB + gi) * C_DIM + col]
                    + red[(2 * GPB + gi) * C_DIM + col]
                    + bhv;
            out[(size_t)(g0 + gi) * C_DIM + col] = lrelu(v);
        }
    }
}

// ---------------- launch: bind inputs by UNIQUE element count ---------------
extern "C" void kernel_launch(void* const* d_in, const int* in_sizes, int n_in,
                              void* d_out, int out_size) {
    const int want[8] = {51200000, 200000, 16384, 64, 192, 3, 196608, 256};
    const void* p[8];
    for (int r = 0; r < 8; r++) p[r] = (r < n_in) ? d_in[r] : nullptr;
    for (int r = 0; r < 8; r++)
        for (int i = 0; i < n_in; i++)
            if (in_sizes[i] == want[r]) { p[r] = d_in[i]; break; }

    const float* x     = (const float*)p[0];
    const int*   batch = (const int*)p[1];
    const float* W1    = (const float*)p[2];
    const float* b1    = (const float*)p[3];
    const float* W2    = (const float*)p[4];
    const float* b2    = (const float*)p[5];
    const float* Wh    = (const float*)p[6];
    const float* bh    = (const float*)p[7];
    float* out = (float*)d_out;

    k_init<<<(G_DIM * K_DIM + 255) / 256, 256>>>();
    k_scores_mma<<<(N_NODES + SC_M - 1) / SC_M, 128>>>(x, batch, W1, b1, W2, b2);
    k_reduce<<<(N_NODES + 255) / 256, 256>>>(batch);
    k_final<<<G_DIM / GPB, KF_THREADS>>>(x, batch, Wh, bh, out);
}

// round 15
// speedup vs baseline: 1.3594x; 1.1453x over previous
#include <cuda_runtime.h>
#include <cuda_fp16.h>
#include <cstdint>

#define N_NODES 200000
#define C_DIM 256
#define H_DIM 64
#define K_DIM 3
#define G_DIM 512

// ---------------- scratch (device globals; no allocation allowed) ----------
__device__ float    g_scores[N_NODES * K_DIM];
__device__ unsigned g_menc[G_DIM * K_DIM];
__device__ float    g_denom[G_DIM * K_DIM];
__device__ int      g_argmin[G_DIM * K_DIM];

// ---------------- helpers --------------------------------------------------
__device__ __forceinline__ unsigned fenc(float f) {
    unsigned u = __float_as_uint(f);
    return u ^ ((u >> 31) ? 0xFFFFFFFFu : 0x80000000u);
}
__device__ __forceinline__ float fdec(unsigned e) {
    unsigned u = (e & 0x80000000u) ? (e ^ 0x80000000u) : ~e;
    return __uint_as_float(u);
}
__device__ __forceinline__ float lrelu(float v) { return v > 0.f ? v : 0.01f * v; }
__device__ __forceinline__ int clampg(int g) { return min(max(g, 0), G_DIM - 1); }

// 2-level fp16 split: v = L0 + L1 (+ O(2^-22 |v|))
__device__ __forceinline__ void split2(float v, uint16_t& e0, uint16_t& e1) {
    __half a = __float2half_rn(v);
    float r = v - __half2float(a);
    __half b = __float2half_rn(r);
    e0 = __half_as_ushort(a);
    e1 = __half_as_ushort(b);
}
__device__ __forceinline__ uint32_t pack2(uint16_t lo, uint16_t hi) {
    return (uint32_t)lo | ((uint32_t)hi << 16);
}
// mma.sync m16n8k16 fp16 -> f32 (sm_80+ PTX; legal on plain compute_103)
__device__ __forceinline__ void mma_f16(float* d, const uint32_t* a, uint2 b) {
    asm volatile(
        "mma.sync.aligned.m16n8k16.row.col.f32.f16.f16.f32 "
        "{%0,%1,%2,%3}, {%4,%5,%6,%7}, {%8,%9}, {%0,%1,%2,%3};"
        : "+f"(d[0]), "+f"(d[1]), "+f"(d[2]), "+f"(d[3])
        : "r"(a[0]), "r"(a[1]), "r"(a[2]), "r"(a[3]), "r"(b.x), "r"(b.y));
}

// ---------------- K0: init reduction buffers -------------------------------
__global__ void k_init() {
    int i = blockIdx.x * blockDim.x + threadIdx.x;
    if (i < G_DIM * K_DIM) {
        g_menc[i]   = 0u;
        g_denom[i]  = 0.f;
        g_argmin[i] = N_NODES;
    }
}

// ---------------- K1: scores via mma.sync fp16 2-level split, 3 terms ------
// CTA: 128 thr (4 warps), 128 rows. Warp: 32 rows x 64 h. K chunks of 32.
#define SC_M 128
#define KC 32
#define A_STRIDE 10       // uint2 per row (8 used + pad)
#define B_STRIDE 10

__global__ __launch_bounds__(128, 4) void k_scores_mma(
    const float* __restrict__ x, const int* __restrict__ batch,
    const float* __restrict__ W1, const float* __restrict__ b1,
    const float* __restrict__ W2, const float* __restrict__ b2)
{
    __shared__ uint2 AU[2][SC_M * A_STRIDE];   // 20480 B
    __shared__ uint2 BU[2][H_DIM * B_STRIDE];  // 10240 B
    __shared__ float W2s[H_DIM * K_DIM];
    __shared__ float b1s[H_DIM];
    __shared__ float b2s[K_DIM];

    const int t    = threadIdx.x;
    const int wid  = t >> 5, lane = t & 31;
    const int g    = lane >> 2, tig = lane & 3;
    const int r0   = blockIdx.x * SC_M;
    const int rw   = wid * 32;

    for (int i = t; i < H_DIM * K_DIM; i += 128) W2s[i] = W2[i];
    if (t < H_DIM) b1s[t] = b1[t];
    if (t < K_DIM) b2s[t] = b2[t];

    float acc[2][8][4];
#pragma unroll
    for (int m = 0; m < 2; m++)
#pragma unroll
        for (int n = 0; n < 8; n++)
#pragma unroll
            for (int e = 0; e < 4; e++) acc[m][n][e] = 0.f;

    // 3 terms: (A0,B0), (A0,B1), (A1,B0)  — A-level grouped for frag reuse
    const int Aseq[3] = {0, 0, 1};
    const int Bseq[3] = {0, 1, 0};

    for (int c0 = 0; c0 < C_DIM; c0 += KC) {
        __syncthreads();
        // ---- stage x tile: 128 rows x 32 k, 2 levels -----------------------
        uint32_t* AW[2] = {(uint32_t*)AU[0], (uint32_t*)AU[1]};
#pragma unroll
        for (int i = 0; i < 8; i++) {
            int f = t + 128 * i;
            int row = f >> 3, c = f & 7;
            float4 v = (r0 + row < N_NODES)
                ? *(const float4*)(x + (size_t)(r0 + row) * C_DIM + c0 + 4 * c)
                : make_float4(0.f, 0.f, 0.f, 0.f);
            uint16_t ex[4][2];
            split2(v.x, ex[0][0], ex[0][1]);
            split2(v.y, ex[1][0], ex[1][1]);
            split2(v.z, ex[2][0], ex[2][1]);
            split2(v.w, ex[3][0], ex[3][1]);
#pragma unroll
            for (int pp = 0; pp < 2; pp++) {
                int p  = 2 * c + pp;
                int kt = p >> 3, rr = p & 7;
                int off = row * (2 * A_STRIDE) + (kt * 4 + (rr & 3)) * 2 + (rr >> 2);
#pragma unroll
                for (int L = 0; L < 2; L++)
                    AW[L][off] = pack2(ex[2 * pp][L], ex[2 * pp + 1][L]);
            }
        }
        // ---- stage W1^T tile: 16 k-pairs x 64 n, 2 levels ------------------
        uint32_t* BW[2] = {(uint32_t*)BU[0], (uint32_t*)BU[1]};
#pragma unroll
        for (int i = 0; i < 8; i++) {
            int idx = t + 128 * i;
            int n = idx & 63, p = idx >> 6;
            float w0 = __ldg(&W1[(size_t)(c0 + 2 * p) * H_DIM + n]);
            float w1 = __ldg(&W1[(size_t)(c0 + 2 * p + 1) * H_DIM + n]);
            uint16_t e0[2], e1[2];
            split2(w0, e0[0], e0[1]);
            split2(w1, e1[0], e1[1]);
            int kt = p >> 3, rr = p & 7;
            int off = n * (2 * B_STRIDE) + (kt * 4 + (rr & 3)) * 2 + (rr >> 2);
#pragma unroll
            for (int L = 0; L < 2; L++)
                BW[L][off] = pack2(e0[L], e1[L]);
        }
        __syncthreads();
        // ---- compute: 2 k16-tiles x 3 terms x (2m x 8n) mma ----------------
#pragma unroll
        for (int kt = 0; kt < 2; kt++) {
            int lastA = -1;
            uint32_t a[2][4];
#pragma unroll
            for (int t3 = 0; t3 < 3; t3++) {
                int La = Aseq[t3], Lb = Bseq[t3];
                if (La != lastA) {
                    lastA = La;
#pragma unroll
                    for (int m = 0; m < 2; m++) {
                        uint2 lo = AU[La][(rw + m * 16 + g) * A_STRIDE + kt * 4 + tig];
                        uint2 hi = AU[La][(rw + m * 16 + g + 8) * A_STRIDE + kt * 4 + tig];
                        a[m][0] = lo.x; a[m][1] = hi.x; a[m][2] = lo.y; a[m][3] = hi.y;
                    }
                }
#pragma unroll
                for (int nt = 0; nt < 8; nt++) {
                    uint2 b = BU[Lb][(nt * 8 + g) * B_STRIDE + kt * 4 + tig];
                    mma_f16(acc[0][nt], a[0], b);
                    mma_f16(acc[1][nt], a[1], b);
                }
            }
        }
    }

    // ---- epilogue: +b1, lrelu, @W2, reduce over tig lanes, atomics ---------
    float sc[4][K_DIM];
#pragma unroll
    for (int s = 0; s < 4; s++)
#pragma unroll
        for (int k = 0; k < K_DIM; k++) sc[s][k] = 0.f;

#pragma unroll
    for (int m = 0; m < 2; m++)
#pragma unroll
        for (int nt = 0; nt < 8; nt++) {
            int cA = nt * 8 + 2 * tig, cB = cA + 1;
            float h0 = lrelu(acc[m][nt][0] + b1s[cA]);
            float h1 = lrelu(acc[m][nt][1] + b1s[cB]);
            float h2 = lrelu(acc[m][nt][2] + b1s[cA]);
            float h3 = lrelu(acc[m][nt][3] + b1s[cB]);
#pragma unroll
            for (int k = 0; k < K_DIM; k++) {
                sc[m * 2 + 0][k] += h0 * W2s[cA * K_DIM + k] + h1 * W2s[cB * K_DIM + k];
                sc[m * 2 + 1][k] += h2 * W2s[cA * K_DIM + k] + h3 * W2s[cB * K_DIM + k];
            }
        }

    const unsigned FULL = 0xFFFFFFFFu;
#pragma unroll
    for (int o = 1; o < 4; o <<= 1)
#pragma unroll
        for (int s = 0; s < 4; s++)
#pragma unroll
            for (int k = 0; k < K_DIM; k++)
                sc[s][k] += __shfl_xor_sync(FULL, sc[s][k], o);

    if (tig == 0) {
#pragma unroll
        for (int s = 0; s < 4; s++) {
            int m = s >> 1, half = s & 1;
            int n = r0 + rw + m * 16 + half * 8 + g;
            if (n < N_NODES) {
                int gb = clampg(batch[n]);
#pragma unroll
                for (int k = 0; k < K_DIM; k++) {
                    float v = sc[s][k] + b2s[k];
                    g_scores[(size_t)n * K_DIM + k] = v;
                    atomicMax(&g_menc[gb * K_DIM + k], fenc(v));
                }
            }
        }
    }
}

// ---------------- K2: exp-sum (denom) + argmin of argmax -------------------
__global__ void k_reduce(const int* __restrict__ batch) {
    int n = blockIdx.x * blockDim.x + threadIdx.x;
    if (n >= N_NODES) return;
    int g = clampg(batch[n]);
#pragma unroll
    for (int k = 0; k < K_DIM; k++) {
        float s = g_scores[(size_t)n * K_DIM + k];
        float m = fdec(g_menc[g * K_DIM + k]);
        float e = expf(s - m);
        atomicAdd(&g_denom[g * K_DIM + k], e);
        if (s == m) atomicMin(&g_argmin[g * K_DIM + k], n);
    }
}

// ---------------- K3: gather + feat@Wh + lrelu (128 blocks, r-split 4) -----
#define GPB 4
#define KF_THREADS 1024
__global__ __launch_bounds__(KF_THREADS) void k_final(
    const float* __restrict__ x, const int* __restrict__ batch,
    const float* __restrict__ Wh, const float* __restrict__ bh,
    float* __restrict__ out)
{
    __shared__ float feat[GPB][K_DIM * C_DIM];
    __shared__ float sg_s[GPB][K_DIM];
    __shared__ int   idx_s[GPB][K_DIM];

    const int t  = threadIdx.x;
    const int g0 = blockIdx.x * GPB;

    if (t < GPB * K_DIM) {
        int gi = t / K_DIM, k = t % K_DIM;
        int g = g0 + gi;
        int idx = min(g_argmin[g * K_DIM + k], N_NODES - 1);
        int gb = clampg(batch[idx]);
        float m = fdec(g_menc[gb * K_DIM + k]);
        float sg = expf(g_scores[(size_t)idx * K_DIM + k] - m) / g_denom[gb * K_DIM + k];
        sg_s[gi][k] = sg;
        idx_s[gi][k] = idx;
    }
    __syncthreads();

    for (int idx = t; idx < GPB * K_DIM * C_DIM; idx += KF_THREADS) {
        int gi = idx / (K_DIM * C_DIM);
        int rem = idx - gi * (K_DIM * C_DIM);
        int k = rem >> 8, c = rem & 255;
        feat[gi][rem] = x[(size_t)idx_s[gi][k] * C_DIM + c] * sg_s[gi][k];
    }
    __syncthreads();

    const int col = t & 255;
    const int rs  = t >> 8;
    float acc[GPB];
#pragma unroll
    for (int gi = 0; gi < GPB; gi++) acc[gi] = 0.f;

    const int rbeg = rs * 192;
#pragma unroll 8
    for (int r = rbeg; r < rbeg + 192; r++) {
        float wv = __ldg(&Wh[(size_t)r * C_DIM + col]);
#pragma unroll
        for (int gi = 0; gi < GPB; gi++) acc[gi] = fmaf(feat[gi][r], wv, acc[gi]);
    }

    __syncthreads();
    float* red = &feat[0][0];
    if (rs > 0) {
#pragma unroll
        for (int gi = 0; gi < GPB; gi++)
            red[((rs - 1) * GPB + gi) * C_DIM + col] = acc[gi];
    }
    __syncthreads();
    if (rs == 0) {
        float bhv = __ldg(&bh[col]);
#pragma unroll
        for (int gi = 0; gi < GPB; gi++) {
            float v = acc[gi]
                    + red[(0 * GPB + gi) * C_DIM + col]
                    + red[(1 * GPB + gi) * C_DIM + col]
                    + red[(2 * GPB + gi) * C_DIM + col]
                    + bhv;
            out[(size_t)(g0 + gi) * C_DIM + col] = lrelu(v);
        }
    }
}

// ---------------- launch: bind inputs by UNIQUE element count ---------------
extern "C" void kernel_launch(void* const* d_in, const int* in_sizes, int n_in,
                              void* d_out, int out_size) {
    const int want[8] = {51200000, 200000, 16384, 64, 192, 3, 196608, 256};
    const void* p[8];
    for (int r = 0; r < 8; r++) p[r] = (r < n_in) ? d_in[r] : nullptr;
    for (int r = 0; r < 8; r++)
        for (int i = 0; i < n_in; i++)
            if (in_sizes[i] == want[r]) { p[r] = d_in[i]; break; }

    const float* x     = (const float*)p[0];
    const int*   batch = (const int*)p[1];
    const float* W1    = (const float*)p[2];
    const float* b1    = (const float*)p[3];
    const float* W2    = (const float*)p[4];
    const float* b2    = (const float*)p[5];
    const float* Wh    = (const float*)p[6];
    const float* bh    = (const float*)p[7];
    float* out = (float*)d_out;

    k_init<<<(G_DIM * K_DIM + 255) / 256, 256>>>();
    k_scores_mma<<<(N_NODES + SC_M - 1) / SC_M, 128>>>(x, batch, W1, b1, W2, b2);
    k_reduce<<<(N_NODES + 255) / 256, 256>>>(batch);
    k_final<<<G_DIM / GPB, KF_THREADS>>>(x, batch, Wh, bh, out);
}

// round 16
// speedup vs baseline: 1.5321x; 1.1270x over previous
#include <cuda_runtime.h>
#include <cuda_fp16.h>
#include <cstdint>

#define N_NODES 200000
#define C_DIM 256
#define H_DIM 64
#define K_DIM 3
#define G_DIM 512

// ---------------- scratch (device globals; no allocation allowed) ----------
__device__ float    g_scores[N_NODES * K_DIM];
__device__ unsigned g_menc[G_DIM * K_DIM];
__device__ float    g_denom[G_DIM * K_DIM];
__device__ int      g_argmin[G_DIM * K_DIM];
// pre-split W1 in mma fragment-slot layout: [lv][ch][n] rows of 18 uint32 (stride 9 uint2)
__device__ __align__(16) uint32_t g_Bsplit[2 * 8 * 64 * 18];

// ---------------- helpers --------------------------------------------------
__device__ __forceinline__ unsigned fenc(float f) {
    unsigned u = __float_as_uint(f);
    return u ^ ((u >> 31) ? 0xFFFFFFFFu : 0x80000000u);
}
__device__ __forceinline__ float fdec(unsigned e) {
    unsigned u = (e & 0x80000000u) ? (e ^ 0x80000000u) : ~e;
    return __uint_as_float(u);
}
__device__ __forceinline__ float lrelu(float v) { return v > 0.f ? v : 0.01f * v; }
__device__ __forceinline__ int clampg(int g) { return min(max(g, 0), G_DIM - 1); }

__device__ __forceinline__ void split2(float v, uint16_t& e0, uint16_t& e1) {
    __half a = __float2half_rn(v);
    float r = v - __half2float(a);
    __half b = __float2half_rn(r);
    e0 = __half_as_ushort(a);
    e1 = __half_as_ushort(b);
}
__device__ __forceinline__ uint32_t pack2(uint16_t lo, uint16_t hi) {
    return (uint32_t)lo | ((uint32_t)hi << 16);
}
__device__ __forceinline__ uint32_t h2u(__half2 h) {
    return *reinterpret_cast<uint32_t*>(&h);
}
// mma.sync m16n8k16 fp16 -> f32
__device__ __forceinline__ void mma_f16(float* d, const uint32_t* a, uint2 b) {
    asm volatile(
        "mma.sync.aligned.m16n8k16.row.col.f32.f16.f16.f32 "
        "{%0,%1,%2,%3}, {%4,%5,%6,%7}, {%8,%9}, {%0,%1,%2,%3};"
        : "+f"(d[0]), "+f"(d[1]), "+f"(d[2]), "+f"(d[3])
        : "r"(a[0]), "r"(a[1]), "r"(a[2]), "r"(a[3]), "r"(b.x), "r"(b.y));
}

// ---------------- K0: init reduction buffers -------------------------------
__global__ void k_init() {
    int i = blockIdx.x * blockDim.x + threadIdx.x;
    if (i < G_DIM * K_DIM) {
        g_menc[i]   = 0u;
        g_denom[i]  = 0.f;
        g_argmin[i] = N_NODES;
    }
}

// ---------------- Kp: pre-split W1 into fragment-slot layout ---------------
__global__ void k_prep(const float* __restrict__ W1) {
    int i = blockIdx.x * blockDim.x + threadIdx.x;
    if (i >= 16384) return;
    int p  = i & 15;          // k-pair within chunk (k = 2p, 2p+1)
    int n  = (i >> 4) & 63;
    int ch = (i >> 10) & 7;
    int lv = i >> 13;
    int k  = ch * 32 + 2 * p;
    float w0 = W1[(size_t)k * H_DIM + n];
    float w1 = W1[(size_t)(k + 1) * H_DIM + n];
    uint16_t h0, l0, h1, l1;
    split2(w0, h0, l0);
    split2(w1, h1, l1);
    uint32_t val = lv ? pack2(l0, l1) : pack2(h0, h1);
    int kt = p >> 3, rr = p & 7;
    int slot = (kt * 4 + (rr & 3)) * 2 + (rr >> 2);
    g_Bsplit[((size_t)(lv * 8 + ch) * 64 + n) * 18 + slot] = val;
}

// ---------------- K1: scores, barrier-free fragment-direct -----------------
#define SC_M 128
#define NBLK ((N_NODES + SC_M - 1) / SC_M)
#define BS_BYTES (2 * 8 * 64 * 18 * 4)   // 73728

__global__ __launch_bounds__(128, 3) void k_scores_mma(
    const float* __restrict__ x, const int* __restrict__ batch,
    const float* __restrict__ b1,
    const float* __restrict__ W2, const float* __restrict__ b2)
{
    extern __shared__ __align__(16) uint32_t BS[];   // 73728 B
    __shared__ float W2s[H_DIM * K_DIM];
    __shared__ float b1s[H_DIM];
    __shared__ float b2s[K_DIM];

    const int t    = threadIdx.x;
    const int wid  = t >> 5, lane = t & 31;
    const int g    = lane >> 2, tig = lane & 3;
    const int r0   = blockIdx.x * SC_M;
    const int rw   = wid * 32;

    // one-time: copy pre-split W1 into smem (uint4 bulk), stage small tables
    {
        const uint4* src = (const uint4*)g_Bsplit;
        uint4* dst = (uint4*)BS;
#pragma unroll
        for (int i = 0; i < 36; i++) dst[t + 128 * i] = src[t + 128 * i];
        for (int i = t; i < H_DIM * K_DIM; i += 128) W2s[i] = W2[i];
        if (t < H_DIM) b1s[t] = b1[t];
        if (t < K_DIM) b2s[t] = b2[t];
    }
    __syncthreads();   // the ONLY barrier

    float acc[2][8][4];
#pragma unroll
    for (int m = 0; m < 2; m++)
#pragma unroll
        for (int n = 0; n < 8; n++)
#pragma unroll
            for (int e = 0; e < 4; e++) acc[m][n][e] = 0.f;

    // thread's 4 rows: rw + g + 8r
    int rows[4];
    bool rok[4];
#pragma unroll
    for (int r = 0; r < 4; r++) {
        rows[r] = r0 + rw + 8 * r + g;
        rok[r] = rows[r] < N_NODES;
    }

    float2 v[4][4];   // [row][s]; col = 2*tig + 8*s
#pragma unroll
    for (int r = 0; r < 4; r++) {
        const float2* src = (const float2*)(x + (size_t)rows[r] * C_DIM + 2 * tig);
#pragma unroll
        for (int s = 0; s < 4; s++)
            v[r][s] = rok[r] ? __ldg(&src[4 * s]) : make_float2(0.f, 0.f);
    }

    const uint2* BSu2 = (const uint2*)BS;

    for (int c = 0; c < 8; c++) {
        // ---- split v -> fp16 fragment regs (packed converts) ---------------
        uint32_t a0[2][2][4], a1[2][2][4];   // [kt][m][j]
#pragma unroll
        for (int kt = 0; kt < 2; kt++)
#pragma unroll
            for (int m = 0; m < 2; m++)
#pragma unroll
                for (int jc = 0; jc < 2; jc++)
#pragma unroll
                    for (int jr = 0; jr < 2; jr++) {
                        float2 vv = v[2 * m + jr][2 * kt + jc];
                        __half2 h = __floats2half2_rn(vv.x, vv.y);
                        float2 up = __half22float2(h);
                        __half2 l = __floats2half2_rn(vv.x - up.x, vv.y - up.y);
                        a0[kt][m][jc * 2 + jr] = h2u(h);
                        a1[kt][m][jc * 2 + jr] = h2u(l);
                    }
        // ---- prefetch next chunk's x (overlaps with compute below) ---------
        if (c < 7) {
#pragma unroll
            for (int r = 0; r < 4; r++) {
                const float2* src = (const float2*)
                    (x + (size_t)rows[r] * C_DIM + (c + 1) * 32 + 2 * tig);
#pragma unroll
                for (int s = 0; s < 4; s++)
                    v[r][s] = rok[r] ? __ldg(&src[4 * s]) : make_float2(0.f, 0.f);
            }
        }
        // ---- compute: per kt: B0 frags -> terms (A0,B0),(A1,B0); B1 -> (A0,B1)
#pragma unroll
        for (int kt = 0; kt < 2; kt++) {
            uint2 bf[8];
#pragma unroll
            for (int nt = 0; nt < 8; nt++)
                bf[nt] = BSu2[((0 * 8 + c) * 64 + nt * 8 + g) * 9 + kt * 4 + tig];
#pragma unroll
            for (int nt = 0; nt < 8; nt++) {
                mma_f16(acc[0][nt], a0[kt][0], bf[nt]);
                mma_f16(acc[1][nt], a0[kt][1], bf[nt]);
            }
#pragma unroll
            for (int nt = 0; nt < 8; nt++) {
                mma_f16(acc[0][nt], a1[kt][0], bf[nt]);
                mma_f16(acc[1][nt], a1[kt][1], bf[nt]);
            }
#pragma unroll
            for (int nt = 0; nt < 8; nt++)
                bf[nt] = BSu2[((1 * 8 + c) * 64 + nt * 8 + g) * 9 + kt * 4 + tig];
#pragma unroll
            for (int nt = 0; nt < 8; nt++) {
                mma_f16(acc[0][nt], a0[kt][0], bf[nt]);
                mma_f16(acc[1][nt], a0[kt][1], bf[nt]);
            }
        }
    }

    // ---- epilogue: +b1, lrelu, @W2, reduce over tig lanes, atomics ---------
    float sc[4][K_DIM];
#pragma unroll
    for (int s = 0; s < 4; s++)
#pragma unroll
        for (int k = 0; k < K_DIM; k++) sc[s][k] = 0.f;

#pragma unroll
    for (int m = 0; m < 2; m++)
#pragma unroll
        for (int nt = 0; nt < 8; nt++) {
            int cA = nt * 8 + 2 * tig, cB = cA + 1;
            float h0 = lrelu(acc[m][nt][0] + b1s[cA]);
            float h1 = lrelu(acc[m][nt][1] + b1s[cB]);
            float h2 = lrelu(acc[m][nt][2] + b1s[cA]);
            float h3 = lrelu(acc[m][nt][3] + b1s[cB]);
#pragma unroll
            for (int k = 0; k < K_DIM; k++) {
                sc[m * 2 + 0][k] += h0 * W2s[cA * K_DIM + k] + h1 * W2s[cB * K_DIM + k];
                sc[m * 2 + 1][k] += h2 * W2s[cA * K_DIM + k] + h3 * W2s[cB * K_DIM + k];
            }
        }

    const unsigned FULL = 0xFFFFFFFFu;
#pragma unroll
    for (int o = 1; o < 4; o <<= 1)
#pragma unroll
        for (int s = 0; s < 4; s++)
#pragma unroll
            for (int k = 0; k < K_DIM; k++)
                sc[s][k] += __shfl_xor_sync(FULL, sc[s][k], o);

    if (tig == 0) {
#pragma unroll
        for (int s = 0; s < 4; s++) {
            // slot s: m = s>>1, half = s&1 -> row = rw + m*16 + half*8 + g
            int n = r0 + rw + (s >> 1) * 16 + (s & 1) * 8 + g;
            if (n < N_NODES) {
                int gb = clampg(batch[n]);
#pragma unroll
                for (int k = 0; k < K_DIM; k++) {
                    float val = sc[s][k] + b2s[k];
                    g_scores[(size_t)n * K_DIM + k] = val;
                    atomicMax(&g_menc[gb * K_DIM + k], fenc(val));
                }
            }
        }
    }
}

// ---------------- K2: exp-sum (denom) + argmin of argmax -------------------
__global__ void k_reduce(const int* __restrict__ batch) {
    int n = blockIdx.x * blockDim.x + threadIdx.x;
    if (n >= N_NODES) return;
    int g = clampg(batch[n]);
#pragma unroll
    for (int k = 0; k < K_DIM; k++) {
        float s = g_scores[(size_t)n * K_DIM + k];
        float m = fdec(g_menc[g * K_DIM + k]);
        float e = expf(s - m);
        atomicAdd(&g_denom[g * K_DIM + k], e);
        if (s == m) atomicMin(&g_argmin[g * K_DIM + k], n);
    }
}

// ---------------- K3: gather + feat@Wh + lrelu (128 blocks, r-split 4) -----
#define GPB 4
#define KF_THREADS 1024
__global__ __launch_bounds__(KF_THREADS) void k_final(
    const float* __restrict__ x, const int* __restrict__ batch,
    const float* __restrict__ Wh, const float* __restrict__ bh,
    float* __restrict__ out)
{
    __shared__ float feat[GPB][K_DIM * C_DIM];
    __shared__ float sg_s[GPB][K_DIM];
    __shared__ int   idx_s[GPB][K_DIM];

    const int t  = threadIdx.x;
    const int g0 = blockIdx.x * GPB;

    if (t < GPB * K_DIM) {
        int gi = t / K_DIM, k = t % K_DIM;
        int g = g0 + gi;
        int idx = min(g_argmin[g * K_DIM + k], N_NODES - 1);
        int gb = clampg(batch[idx]);
        float m = fdec(g_menc[gb * K_DIM + k]);
        float sg = expf(g_scores[(size_t)idx * K_DIM + k] - m) / g_denom[gb * K_DIM + k];
        sg_s[gi][k] = sg;
        idx_s[gi][k] = idx;
    }
    __syncthreads();

    for (int idx = t; idx < GPB * K_DIM * C_DIM; idx += KF_THREADS) {
        int gi = idx / (K_DIM * C_DIM);
        int rem = idx - gi * (K_DIM * C_DIM);
        int k = rem >> 8, c = rem & 255;
        feat[gi][rem] = x[(size_t)idx_s[gi][k] * C_DIM + c] * sg_s[gi][k];
    }
    __syncthreads();

    const int col = t & 255;
    const int rs  = t >> 8;
    float acc[GPB];
#pragma unroll
    for (int gi = 0; gi < GPB; gi++) acc[gi] = 0.f;

    const int rbeg = rs * 192;
#pragma unroll 8
    for (int r = rbeg; r < rbeg + 192; r++) {
        float wv = __ldg(&Wh[(size_t)r * C_DIM + col]);
#pragma unroll
        for (int gi = 0; gi < GPB; gi++) acc[gi] = fmaf(feat[gi][r], wv, acc[gi]);
    }

    __syncthreads();
    float* red = &feat[0][0];
    if (rs > 0) {
#pragma unroll
        for (int gi = 0; gi < GPB; gi++)
            red[((rs - 1) * GPB + gi) * C_DIM + col] = acc[gi];
    }
    __syncthreads();
    if (rs == 0) {
        float bhv = __ldg(&bh[col]);
#pragma unroll
        for (int gi = 0; gi < GPB; gi++) {
            float v = acc[gi]
                    + red[(0 * GPB + gi) * C_DIM + col]
                    + red[(1 * GPB + gi) * C_DIM + col]
                    + red[(2 * GPB + gi) * C_DIM + col]
                    + bhv;
            out[(size_t)(g0 + gi) * C_DIM + col] = lrelu(v);
        }
    }
}

// ---------------- launch: bind inputs by UNIQUE element count ---------------
extern "C" void kernel_launch(void* const* d_in, const int* in_sizes, int n_in,
                              void* d_out, int out_size) {
    const int want[8] = {51200000, 200000, 16384, 64, 192, 3, 196608, 256};
    const void* p[8];
    for (int r = 0; r < 8; r++) p[r] = (r < n_in) ? d_in[r] : nullptr;
    for (int r = 0; r < 8; r++)
        for (int i = 0; i < n_in; i++)
            if (in_sizes[i] == want[r]) { p[r] = d_in[i]; break; }

    const float* x     = (const float*)p[0];
    const int*   batch = (const int*)p[1];
    const float* W1    = (const float*)p[2];
    const float* b1    = (const float*)p[3];
    const float* W2    = (const float*)p[4];
    const float* b2    = (const float*)p[5];
    const float* Wh    = (const float*)p[6];
    const float* bh    = (const float*)p[7];
    float* out = (float*)d_out;

    cudaFuncSetAttribute(k_scores_mma,
                         cudaFuncAttributeMaxDynamicSharedMemorySize, BS_BYTES);

    k_init<<<(G_DIM * K_DIM + 255) / 256, 256>>>();
    k_prep<<<(16384 + 255) / 256, 256>>>(W1);
    k_scores_mma<<<NBLK, 128, BS_BYTES>>>(x, batch, b1, W2, b2);
    k_reduce<<<(N_NODES + 255) / 256, 256>>>(batch);
    k_final<<<G_DIM / GPB, KF_THREADS>>>(x, batch, Wh, bh, out);
}

// round 17
// speedup vs baseline: 3.1517x; 2.0572x over previous
#include <cuda_runtime.h>
#include <cuda_fp16.h>
#include <cstdint>

#define N_NODES 200000
#define C_DIM 256
#define H_DIM 64
#define K_DIM 3
#define G_DIM 512

// ---------------- scratch (device globals; no allocation allowed) ----------
__device__ float    g_scores[N_NODES * K_DIM];
__device__ unsigned g_menc[G_DIM * K_DIM];
__device__ float    g_denom[G_DIM * K_DIM];
__device__ int      g_argmin[G_DIM * K_DIM];
// pre-split W1 in mma fragment-slot layout: [lv][ch][n] rows of 18 uint32
__device__ __align__(16) uint32_t g_Bsplit[2 * 8 * 64 * 18];

// ---------------- helpers --------------------------------------------------
__device__ __forceinline__ unsigned fenc(float f) {
    unsigned u = __float_as_uint(f);
    return u ^ ((u >> 31) ? 0xFFFFFFFFu : 0x80000000u);
}
__device__ __forceinline__ float fdec(unsigned e) {
    unsigned u = (e & 0x80000000u) ? (e ^ 0x80000000u) : ~e;
    return __uint_as_float(u);
}
__device__ __forceinline__ float lrelu(float v) { return v > 0.f ? v : 0.01f * v; }
__device__ __forceinline__ int clampg(int g) { return min(max(g, 0), G_DIM - 1); }

__device__ __forceinline__ void split2(float v, uint16_t& e0, uint16_t& e1) {
    __half a = __float2half_rn(v);
    float r = v - __half2float(a);
    __half b = __float2half_rn(r);
    e0 = __half_as_ushort(a);
    e1 = __half_as_ushort(b);
}
__device__ __forceinline__ uint32_t pack2(uint16_t lo, uint16_t hi) {
    return (uint32_t)lo | ((uint32_t)hi << 16);
}
__device__ __forceinline__ uint32_t h2u(__half2 h) {
    return *reinterpret_cast<uint32_t*>(&h);
}
__device__ __forceinline__ void mma_f16(float* d, const uint32_t* a, uint2 b) {
    asm volatile(
        "mma.sync.aligned.m16n8k16.row.col.f32.f16.f16.f32 "
        "{%0,%1,%2,%3}, {%4,%5,%6,%7}, {%8,%9}, {%0,%1,%2,%3};"
        : "+f"(d[0]), "+f"(d[1]), "+f"(d[2]), "+f"(d[3])
        : "r"(a[0]), "r"(a[1]), "r"(a[2]), "r"(a[3]), "r"(b.x), "r"(b.y));
}

// ---------------- K0: init reduction buffers -------------------------------
__global__ void k_init() {
    int i = blockIdx.x * blockDim.x + threadIdx.x;
    if (i < G_DIM * K_DIM) {
        g_menc[i]   = 0u;
        g_denom[i]  = 0.f;
        g_argmin[i] = N_NODES;
    }
}

// ---------------- Kp: pre-split W1 into fragment-slot layout ---------------
__global__ void k_prep(const float* __restrict__ W1) {
    int i = blockIdx.x * blockDim.x + threadIdx.x;
    if (i >= 16384) return;
    int p  = i & 15;
    int n  = (i >> 4) & 63;
    int ch = (i >> 10) & 7;
    int lv = i >> 13;
    int k  = ch * 32 + 2 * p;
    float w0 = W1[(size_t)k * H_DIM + n];
    float w1 = W1[(size_t)(k + 1) * H_DIM + n];
    uint16_t h0, l0, h1, l1;
    split2(w0, h0, l0);
    split2(w1, h1, l1);
    uint32_t val = lv ? pack2(l0, l1) : pack2(h0, h1);
    int kt = p >> 3, rr = p & 7;
    int slot = (kt * 4 + (rr & 3)) * 2 + (rr >> 2);
    g_Bsplit[((size_t)(lv * 8 + ch) * 64 + n) * 18 + slot] = val;
}

// ---------------- K1: scores, fragment-direct + warp-agg atomicMax ---------
#define SC_M 128
#define NBLK ((N_NODES + SC_M - 1) / SC_M)
#define BS_BYTES (2 * 8 * 64 * 18 * 4)   // 73728

__global__ __launch_bounds__(128, 3) void k_scores_mma(
    const float* __restrict__ x, const int* __restrict__ batch,
    const float* __restrict__ b1,
    const float* __restrict__ W2, const float* __restrict__ b2)
{
    extern __shared__ __align__(16) uint32_t BS[];
    __shared__ float W2s[H_DIM * K_DIM];
    __shared__ float b1s[H_DIM];
    __shared__ float b2s[K_DIM];

    const int t    = threadIdx.x;
    const int wid  = t >> 5, lane = t & 31;
    const int g    = lane >> 2, tig = lane & 3;
    const int r0   = blockIdx.x * SC_M;
    const int rw   = wid * 32;

    {
        const uint4* src = (const uint4*)g_Bsplit;
        uint4* dst = (uint4*)BS;
#pragma unroll
        for (int i = 0; i < 36; i++) dst[t + 128 * i] = src[t + 128 * i];
        for (int i = t; i < H_DIM * K_DIM; i += 128) W2s[i] = W2[i];
        if (t < H_DIM) b1s[t] = b1[t];
        if (t < K_DIM) b2s[t] = b2[t];
    }
    __syncthreads();   // the ONLY barrier

    float acc[2][8][4];
#pragma unroll
    for (int m = 0; m < 2; m++)
#pragma unroll
        for (int n = 0; n < 8; n++)
#pragma unroll
            for (int e = 0; e < 4; e++) acc[m][n][e] = 0.f;

    int rows[4];
    bool rok[4];
#pragma unroll
    for (int r = 0; r < 4; r++) {
        rows[r] = r0 + rw + 8 * r + g;
        rok[r] = rows[r] < N_NODES;
    }

    float2 v[4][4];
#pragma unroll
    for (int r = 0; r < 4; r++) {
        const float2* src = (const float2*)(x + (size_t)rows[r] * C_DIM + 2 * tig);
#pragma unroll
        for (int s = 0; s < 4; s++)
            v[r][s] = rok[r] ? __ldg(&src[4 * s]) : make_float2(0.f, 0.f);
    }

    const uint2* BSu2 = (const uint2*)BS;

    for (int c = 0; c < 8; c++) {
        uint32_t a0[2][2][4], a1[2][2][4];
#pragma unroll
        for (int kt = 0; kt < 2; kt++)
#pragma unroll
            for (int m = 0; m < 2; m++)
#pragma unroll
                for (int jc = 0; jc < 2; jc++)
#pragma unroll
                    for (int jr = 0; jr < 2; jr++) {
                        float2 vv = v[2 * m + jr][2 * kt + jc];
                        __half2 h = __floats2half2_rn(vv.x, vv.y);
                        float2 up = __half22float2(h);
                        __half2 l = __floats2half2_rn(vv.x - up.x, vv.y - up.y);
                        a0[kt][m][jc * 2 + jr] = h2u(h);
                        a1[kt][m][jc * 2 + jr] = h2u(l);
                    }
        if (c < 7) {
#pragma unroll
            for (int r = 0; r < 4; r++) {
                const float2* src = (const float2*)
                    (x + (size_t)rows[r] * C_DIM + (c + 1) * 32 + 2 * tig);
#pragma unroll
                for (int s = 0; s < 4; s++)
                    v[r][s] = rok[r] ? __ldg(&src[4 * s]) : make_float2(0.f, 0.f);
            }
        }
#pragma unroll
        for (int kt = 0; kt < 2; kt++) {
            uint2 bf[8];
#pragma unroll
            for (int nt = 0; nt < 8; nt++)
                bf[nt] = BSu2[((0 * 8 + c) * 64 + nt * 8 + g) * 9 + kt * 4 + tig];
#pragma unroll
            for (int nt = 0; nt < 8; nt++) {
                mma_f16(acc[0][nt], a0[kt][0], bf[nt]);
                mma_f16(acc[1][nt], a0[kt][1], bf[nt]);
            }
#pragma unroll
            for (int nt = 0; nt < 8; nt++) {
                mma_f16(acc[0][nt], a1[kt][0], bf[nt]);
                mma_f16(acc[1][nt], a1[kt][1], bf[nt]);
            }
#pragma unroll
            for (int nt = 0; nt < 8; nt++)
                bf[nt] = BSu2[((1 * 8 + c) * 64 + nt * 8 + g) * 9 + kt * 4 + tig];
#pragma unroll
            for (int nt = 0; nt < 8; nt++) {
                mma_f16(acc[0][nt], a0[kt][0], bf[nt]);
                mma_f16(acc[1][nt], a0[kt][1], bf[nt]);
            }
        }
    }

    // ---- epilogue: +b1, lrelu, @W2, tig-butterfly, warp-agg atomicMax ------
    float sc[4][K_DIM];
#pragma unroll
    for (int s = 0; s < 4; s++)
#pragma unroll
        for (int k = 0; k < K_DIM; k++) sc[s][k] = 0.f;

#pragma unroll
    for (int m = 0; m < 2; m++)
#pragma unroll
        for (int nt = 0; nt < 8; nt++) {
            int cA = nt * 8 + 2 * tig, cB = cA + 1;
            float h0 = lrelu(acc[m][nt][0] + b1s[cA]);
            float h1 = lrelu(acc[m][nt][1] + b1s[cB]);
            float h2 = lrelu(acc[m][nt][2] + b1s[cA]);
            float h3 = lrelu(acc[m][nt][3] + b1s[cB]);
#pragma unroll
            for (int k = 0; k < K_DIM; k++) {
                sc[m * 2 + 0][k] += h0 * W2s[cA * K_DIM + k] + h1 * W2s[cB * K_DIM + k];
                sc[m * 2 + 1][k] += h2 * W2s[cA * K_DIM + k] + h3 * W2s[cB * K_DIM + k];
            }
        }

    const unsigned FULL = 0xFFFFFFFFu;
#pragma unroll
    for (int o = 1; o < 4; o <<= 1)      // after this, ALL lanes hold full sums
#pragma unroll
        for (int s = 0; s < 4; s++)
#pragma unroll
            for (int k = 0; k < K_DIM; k++)
                sc[s][k] += __shfl_xor_sync(FULL, sc[s][k], o);

    // final scores + encodings for this lane's 4 row-slots
    float val[4][K_DIM];
    int   grp[4];
    bool  vok[4];
#pragma unroll
    for (int s = 0; s < 4; s++) {
        int n = r0 + rw + (s >> 1) * 16 + (s & 1) * 8 + g;
        vok[s] = n < N_NODES;
        grp[s] = vok[s] ? clampg(batch[n]) : -1;
#pragma unroll
        for (int k = 0; k < K_DIM; k++) val[s][k] = sc[s][k] + b2s[k];
        if (vok[s] && tig == 0) {
#pragma unroll
            for (int k = 0; k < K_DIM; k++)
                g_scores[(size_t)n * K_DIM + k] = val[s][k];
        }
    }

    int g0 = __shfl_sync(FULL, grp[0], 0);
    bool uni = __all_sync(FULL,
        grp[0] == g0 && grp[1] == g0 && grp[2] == g0 && grp[3] == g0);
    if (uni) {
        if (g0 >= 0) {
#pragma unroll
            for (int k = 0; k < K_DIM; k++) {
                unsigned e = max(max(fenc(val[0][k]), fenc(val[1][k])),
                                 max(fenc(val[2][k]), fenc(val[3][k])));
#pragma unroll
                for (int o = 16; o; o >>= 1)
                    e = max(e, __shfl_xor_sync(FULL, e, o));
                if (lane == 0) atomicMax(&g_menc[g0 * K_DIM + k], e);
            }
        }
    } else if (tig == 0) {
#pragma unroll
        for (int s = 0; s < 4; s++)
            if (vok[s])
#pragma unroll
                for (int k = 0; k < K_DIM; k++)
                    atomicMax(&g_menc[grp[s] * K_DIM + k], fenc(val[s][k]));
    }
}

// ---------------- K2: exp-sum (denom) + argmin, warp-aggregated ------------
__global__ void k_reduce(const int* __restrict__ batch) {
    int n = blockIdx.x * blockDim.x + threadIdx.x;
    bool valid = n < N_NODES;
    int g = valid ? clampg(batch[n]) : -1;
    float e[K_DIM];
#pragma unroll
    for (int k = 0; k < K_DIM; k++) {
        e[k] = 0.f;
        if (valid) {
            float s = g_scores[(size_t)n * K_DIM + k];
            float m = fdec(g_menc[g * K_DIM + k]);
            e[k] = expf(s - m);
            if (s == m) atomicMin(&g_argmin[g * K_DIM + k], n);  // rare
        }
    }
    const unsigned FULL = 0xFFFFFFFFu;
    int gl0 = __shfl_sync(FULL, g, 0);
    bool uni = __all_sync(FULL, g == gl0);
    if (uni) {
        if (gl0 >= 0) {
#pragma unroll
            for (int k = 0; k < K_DIM; k++) {
                float v = e[k];
#pragma unroll
                for (int o = 16; o; o >>= 1) v += __shfl_xor_sync(FULL, v, o);
                if ((threadIdx.x & 31) == 0) atomicAdd(&g_denom[gl0 * K_DIM + k], v);
            }
        }
    } else if (valid) {
#pragma unroll
        for (int k = 0; k < K_DIM; k++) atomicAdd(&g_denom[g * K_DIM + k], e[k]);
    }
}

// ---------------- K3: gather + feat@Wh + lrelu (128 blocks, r-split 4) -----
#define GPB 4
#define KF_THREADS 1024
__global__ __launch_bounds__(KF_THREADS) void k_final(
    const float* __restrict__ x, const int* __restrict__ batch,
    const float* __restrict__ Wh, const float* __restrict__ bh,
    float* __restrict__ out)
{
    __shared__ float feat[GPB][K_DIM * C_DIM];
    __shared__ float sg_s[GPB][K_DIM];
    __shared__ int   idx_s[GPB][K_DIM];

    const int t  = threadIdx.x;
    const int g0 = blockIdx.x * GPB;

    if (t < GPB * K_DIM) {
        int gi = t / K_DIM, k = t % K_DIM;
        int g = g0 + gi;
        int idx = min(g_argmin[g * K_DIM + k], N_NODES - 1);
        int gb = clampg(batch[idx]);
        float m = fdec(g_menc[gb * K_DIM + k]);
        float sg = expf(g_scores[(size_t)idx * K_DIM + k] - m) / g_denom[gb * K_DIM + k];
        sg_s[gi][k] = sg;
        idx_s[gi][k] = idx;
    }
    __syncthreads();

    for (int idx = t; idx < GPB * K_DIM * C_DIM; idx += KF_THREADS) {
        int gi = idx / (K_DIM * C_DIM);
        int rem = idx - gi * (K_DIM * C_DIM);
        int k = rem >> 8, c = rem & 255;
        feat[gi][rem] = x[(size_t)idx_s[gi][k] * C_DIM + c] * sg_s[gi][k];
    }
    __syncthreads();

    const int col = t & 255;
    const int rs  = t >> 8;
    float acc[GPB];
#pragma unroll
    for (int gi = 0; gi < GPB; gi++) acc[gi] = 0.f;

    const int rbeg = rs * 192;
#pragma unroll 8
    for (int r = rbeg; r < rbeg + 192; r++) {
        float wv = __ldg(&Wh[(size_t)r * C_DIM + col]);
#pragma unroll
        for (int gi = 0; gi < GPB; gi++) acc[gi] = fmaf(feat[gi][r], wv, acc[gi]);
    }

    __syncthreads();
    float* red = &feat[0][0];
    if (rs > 0) {
#pragma unroll
        for (int gi = 0; gi < GPB; gi++)
            red[((rs - 1) * GPB + gi) * C_DIM + col] = acc[gi];
    }
    __syncthreads();
    if (rs == 0) {
        float bhv = __ldg(&bh[col]);
#pragma unroll
        for (int gi = 0; gi < GPB; gi++) {
            float v = acc[gi]
                    + red[(0 * GPB + gi) * C_DIM + col]
                    + red[(1 * GPB + gi) * C_DIM + col]
                    + red[(2 * GPB + gi) * C_DIM + col]
                    + bhv;
            out[(size_t)(g0 + gi) * C_DIM + col] = lrelu(v);
        }
    }
}

// ---------------- launch: bind inputs by UNIQUE element count ---------------
extern "C" void kernel_launch(void* const* d_in, const int* in_sizes, int n_in,
                              void* d_out, int out_size) {
    const int want[8] = {51200000, 200000, 16384, 64, 192, 3, 196608, 256};
    const void* p[8];
    for (int r = 0; r < 8; r++) p[r] = (r < n_in) ? d_in[r] : nullptr;
    for (int r = 0; r < 8; r++)
        for (int i = 0; i < n_in; i++)
            if (in_sizes[i] == want[r]) { p[r] = d_in[i]; break; }

    const float* x     = (const float*)p[0];
    const int*   batch = (const int*)p[1];
    const float* W1    = (const float*)p[2];
    const float* b1    = (const float*)p[3];
    const float* W2    = (const float*)p[4];
    const float* b2    = (const float*)p[5];
    const float* Wh    = (const float*)p[6];
    const float* bh    = (const float*)p[7];
    float* out = (float*)d_out;

    cudaFuncSetAttribute(k_scores_mma,
                         cudaFuncAttributeMaxDynamicSharedMemorySize, BS_BYTES);

    k_init<<<(G_DIM * K_DIM + 255) / 256, 256>>>();
    k_prep<<<(16384 + 255) / 256, 256>>>(W1);
    k_scores_mma<<<NBLK, 128, BS_BYTES>>>(x, batch, b1, W2, b2);
    k_reduce<<<(N_NODES + 255) / 256, 256>>>(batch);
    k_final<<<G_DIM / GPB, KF_THREADS>>>(x, batch, Wh, bh, out);
}